// round 1
// baseline (speedup 1.0000x reference)
#include <cuda_runtime.h>

#define NB 4
#define NUM_OP 6
#define LANG_DIM 256
#define NHIDDEN 128
#define HH 128
#define WW 128
#define HWSZ (HH * WW)        // 16384
#define NC 128
#define SEM_CH (NUM_OP + 2)   // 8

// Per-batch folded coefficients: gw[b][k] = gamma[b][k]*wr[k], bw[b][k] = beta[b][k]*wr[k]
__device__ float g_gw[NB][NUM_OP];
__device__ float g_bw[NB][NUM_OP];
__device__ float g_wrsum;
__device__ float g_br;

// ---------------------------------------------------------------------------
// Kernel 1: tiny per-batch MLP -> folded coefficients. 4 blocks x 128 threads.
// ---------------------------------------------------------------------------
__global__ void coef_kernel(const float* __restrict__ lang,
                            const float* __restrict__ Ws, const float* __restrict__ bs,
                            const float* __restrict__ Wg, const float* __restrict__ bg,
                            const float* __restrict__ Wb, const float* __restrict__ bb,
                            const float* __restrict__ Wr, const float* __restrict__ br) {
    const int b = blockIdx.x;
    const int n = threadIdx.x;          // 0..127 (NHIDDEN)
    __shared__ float actv[NHIDDEN];

    // actv[n] = bs[n] + lang[b,:] . Ws[n,:]
    const float* lb  = lang + b * LANG_DIM;
    const float* wsr = Ws + n * LANG_DIM;
    float acc = bs[n];
#pragma unroll 8
    for (int l = 0; l < LANG_DIM; ++l) acc += lb[l] * wsr[l];
    actv[n] = acc;
    __syncthreads();

    if (n < NUM_OP) {
        const float* wgr = Wg + n * NHIDDEN;
        const float* wbr = Wb + n * NHIDDEN;
        float g = bg[n], bt = bb[n];
#pragma unroll 8
        for (int h = 0; h < NHIDDEN; ++h) {
            float a = actv[h];
            g  += a * wgr[h];
            bt += a * wbr[h];
        }
        const float wr = Wr[n];
        g_gw[b][n] = g * wr;
        g_bw[b][n] = bt * wr;
    }
    if (b == 0 && n == 0) {
        float s = 0.0f;
#pragma unroll
        for (int k = 0; k < NUM_OP; ++k) s += Wr[k];
        g_wrsum = s;
        g_br = br[0];
    }
}

// ---------------------------------------------------------------------------
// Kernel 2: out[b,c,hw] = x[b,c,hw]*scale[b,hw] + shift[b,hw]
// Each thread: one float4 of hw, computes scale/shift once, streams CCHUNK
// channels. Grid: (HWSZ/4/256, NB, NC/CCHUNK) = (16, 4, 4) -> 256 blocks.
// ---------------------------------------------------------------------------
#define CCHUNK 32
#define TPB 256

__global__ __launch_bounds__(TPB) void main_kernel(const float* __restrict__ x,
                                                   const float* __restrict__ sem,
                                                   float* __restrict__ out) {
    const int b   = blockIdx.y;
    const int c0  = blockIdx.z * CCHUNK;
    const int hw4 = blockIdx.x * TPB + threadIdx.x;   // [0, HWSZ/4)

    float gw[NUM_OP], bw[NUM_OP];
#pragma unroll
    for (int k = 0; k < NUM_OP; ++k) { gw[k] = g_gw[b][k]; bw[k] = g_bw[b][k]; }
    const float wrsum = g_wrsum;
    const float brv   = g_br;

    float4 scale = make_float4(wrsum, wrsum, wrsum, wrsum);
    float4 shift = make_float4(brv, brv, brv, brv);

    const float4* semb =
        reinterpret_cast<const float4*>(sem + (size_t)b * SEM_CH * HWSZ + 2 * HWSZ) + hw4;
#pragma unroll
    for (int k = 0; k < NUM_OP; ++k) {
        float4 s = semb[(size_t)k * (HWSZ / 4)];
        scale.x += gw[k] * s.x;  scale.y += gw[k] * s.y;
        scale.z += gw[k] * s.z;  scale.w += gw[k] * s.w;
        shift.x += bw[k] * s.x;  shift.y += bw[k] * s.y;
        shift.z += bw[k] * s.z;  shift.w += bw[k] * s.w;
    }

    const float4* xb = reinterpret_cast<const float4*>(x + (size_t)b * NC * HWSZ) + hw4;
    float4*       ob = reinterpret_cast<float4*>(out + (size_t)b * NC * HWSZ) + hw4;

#pragma unroll 4
    for (int c = c0; c < c0 + CCHUNK; ++c) {
        float4 xv = xb[(size_t)c * (HWSZ / 4)];
        float4 o;
        o.x = xv.x * scale.x + shift.x;
        o.y = xv.y * scale.y + shift.y;
        o.z = xv.z * scale.z + shift.z;
        o.w = xv.w * scale.w + shift.w;
        ob[(size_t)c * (HWSZ / 4)] = o;
    }
}

// ---------------------------------------------------------------------------
extern "C" void kernel_launch(void* const* d_in, const int* in_sizes, int n_in,
                              void* d_out, int out_size) {
    const float* x    = (const float*)d_in[0];
    const float* lang = (const float*)d_in[1];
    const float* sem  = (const float*)d_in[2];
    const float* Ws   = (const float*)d_in[3];
    const float* bs   = (const float*)d_in[4];
    const float* Wg   = (const float*)d_in[5];
    const float* bg   = (const float*)d_in[6];
    const float* Wb   = (const float*)d_in[7];
    const float* bb   = (const float*)d_in[8];
    const float* Wr   = (const float*)d_in[9];
    const float* br   = (const float*)d_in[10];
    float* out = (float*)d_out;

    coef_kernel<<<NB, NHIDDEN>>>(lang, Ws, bs, Wg, bg, Wb, bb, Wr, br);

    dim3 grid(HWSZ / 4 / TPB, NB, NC / CCHUNK);
    main_kernel<<<grid, TPB>>>(x, sem, out);
}

// round 2
// speedup vs baseline: 1.8889x; 1.8889x over previous
#include <cuda_runtime.h>

#define NB 4
#define NUM_OP 6
#define LANG_DIM 256
#define NHIDDEN 128
#define HH 128
#define WW 128
#define HWSZ (HH * WW)        // 16384
#define NC 128
#define SEM_CH (NUM_OP + 2)   // 8

// Per-batch folded coefficients: gw[b][k] = gamma[b][k]*wr[k], bw[b][k] = beta[b][k]*wr[k]
__device__ float g_gw[NB][NUM_OP];
__device__ float g_bw[NB][NUM_OP];
__device__ float g_wrsum;
__device__ float g_br;

// ---------------------------------------------------------------------------
// Kernel 1: per-batch MLP -> folded coefficients. 4 blocks x 256 threads.
// Warp-per-output with lane-parallel partial sums: ALL weight loads coalesced.
// ---------------------------------------------------------------------------
__global__ __launch_bounds__(256) void coef_kernel(
    const float* __restrict__ lang,
    const float* __restrict__ Ws, const float* __restrict__ bs,
    const float* __restrict__ Wg, const float* __restrict__ bg,
    const float* __restrict__ Wb, const float* __restrict__ bb,
    const float* __restrict__ Wr, const float* __restrict__ br) {
    const int b    = blockIdx.x;
    const int tid  = threadIdx.x;
    const int warp = tid >> 5;
    const int lane = tid & 31;

    __shared__ float slang[LANG_DIM];
    __shared__ float actv[NHIDDEN];

    // Stage lang[b,:] (coalesced)
    slang[tid] = lang[b * LANG_DIM + tid];
    __syncthreads();

    // actv[n] = bs[n] + lang . Ws[n,:].  Warp w handles n = w, w+8, ... (16 outputs).
    // Lanes read Ws[n, lane + 32j] -> fully coalesced 128B per load.
#pragma unroll
    for (int i = 0; i < NHIDDEN / 8; ++i) {
        const int n = warp + 8 * i;
        const float* wsr = Ws + n * LANG_DIM;
        float p = 0.0f;
#pragma unroll
        for (int j = 0; j < LANG_DIM / 32; ++j)
            p += wsr[lane + 32 * j] * slang[lane + 32 * j];
        // warp reduce
#pragma unroll
        for (int off = 16; off > 0; off >>= 1)
            p += __shfl_xor_sync(0xFFFFFFFFu, p, off);
        if (lane == 0) actv[n] = p + bs[n];
    }
    __syncthreads();

    // gamma[k], beta[k]: warp k (k<6) does both 128-dots with coalesced loads.
    if (warp < NUM_OP) {
        const int k = warp;
        const float* wgr = Wg + k * NHIDDEN;
        const float* wbr = Wb + k * NHIDDEN;
        float pg = 0.0f, pb = 0.0f;
#pragma unroll
        for (int j = 0; j < NHIDDEN / 32; ++j) {
            float a = actv[lane + 32 * j];
            pg += a * wgr[lane + 32 * j];
            pb += a * wbr[lane + 32 * j];
        }
#pragma unroll
        for (int off = 16; off > 0; off >>= 1) {
            pg += __shfl_xor_sync(0xFFFFFFFFu, pg, off);
            pb += __shfl_xor_sync(0xFFFFFFFFu, pb, off);
        }
        if (lane == 0) {
            const float wr = Wr[k];
            g_gw[b][k] = (pg + bg[k]) * wr;
            g_bw[b][k] = (pb + bb[k]) * wr;
        }
    } else if (warp == 6 && lane == 0 && b == 0) {
        float s = 0.0f;
#pragma unroll
        for (int k = 0; k < NUM_OP; ++k) s += Wr[k];
        g_wrsum = s;
        g_br = br[0];
    }
}

// ---------------------------------------------------------------------------
// Kernel 2: out[b,c,hw] = x[b,c,hw]*scale[b,hw] + shift[b,hw]
// Each thread: one float4 of hw, computes scale/shift once, streams CCHUNK
// channels. Grid: (HWSZ/4/256, NB, NC/CCHUNK) = (16, 4, 8) -> 512 blocks.
// ---------------------------------------------------------------------------
#define CCHUNK 16
#define TPB 256

__global__ __launch_bounds__(TPB) void main_kernel(const float* __restrict__ x,
                                                   const float* __restrict__ sem,
                                                   float* __restrict__ out) {
    const int b   = blockIdx.y;
    const int c0  = blockIdx.z * CCHUNK;
    const int hw4 = blockIdx.x * TPB + threadIdx.x;   // [0, HWSZ/4)

    float gw[NUM_OP], bw[NUM_OP];
#pragma unroll
    for (int k = 0; k < NUM_OP; ++k) { gw[k] = g_gw[b][k]; bw[k] = g_bw[b][k]; }
    const float wrsum = g_wrsum;
    const float brv   = g_br;

    float4 scale = make_float4(wrsum, wrsum, wrsum, wrsum);
    float4 shift = make_float4(brv, brv, brv, brv);

    const float4* semb =
        reinterpret_cast<const float4*>(sem + (size_t)b * SEM_CH * HWSZ + 2 * HWSZ) + hw4;
#pragma unroll
    for (int k = 0; k < NUM_OP; ++k) {
        float4 s = semb[(size_t)k * (HWSZ / 4)];
        scale.x += gw[k] * s.x;  scale.y += gw[k] * s.y;
        scale.z += gw[k] * s.z;  scale.w += gw[k] * s.w;
        shift.x += bw[k] * s.x;  shift.y += bw[k] * s.y;
        shift.z += bw[k] * s.z;  shift.w += bw[k] * s.w;
    }

    const float4* xb = reinterpret_cast<const float4*>(x + (size_t)b * NC * HWSZ) + hw4;
    float4*       ob = reinterpret_cast<float4*>(out + (size_t)b * NC * HWSZ) + hw4;

#pragma unroll 8
    for (int c = c0; c < c0 + CCHUNK; ++c) {
        float4 xv = xb[(size_t)c * (HWSZ / 4)];
        float4 o;
        o.x = xv.x * scale.x + shift.x;
        o.y = xv.y * scale.y + shift.y;
        o.z = xv.z * scale.z + shift.z;
        o.w = xv.w * scale.w + shift.w;
        ob[(size_t)c * (HWSZ / 4)] = o;
    }
}

// ---------------------------------------------------------------------------
extern "C" void kernel_launch(void* const* d_in, const int* in_sizes, int n_in,
                              void* d_out, int out_size) {
    const float* x    = (const float*)d_in[0];
    const float* lang = (const float*)d_in[1];
    const float* sem  = (const float*)d_in[2];
    const float* Ws   = (const float*)d_in[3];
    const float* bs   = (const float*)d_in[4];
    const float* Wg   = (const float*)d_in[5];
    const float* bg   = (const float*)d_in[6];
    const float* Wb   = (const float*)d_in[7];
    const float* bb   = (const float*)d_in[8];
    const float* Wr   = (const float*)d_in[9];
    const float* br   = (const float*)d_in[10];
    float* out = (float*)d_out;

    coef_kernel<<<NB, 256>>>(lang, Ws, bs, Wg, bg, Wb, bb, Wr, br);

    dim3 grid(HWSZ / 4 / TPB, NB, NC / CCHUNK);
    main_kernel<<<grid, TPB>>>(x, sem, out);
}

// round 3
// speedup vs baseline: 2.1292x; 1.1272x over previous
#include <cuda_runtime.h>

#define NB 4
#define NUM_OP 6
#define LANG_DIM 256
#define NHIDDEN 128
#define HH 128
#define WW 128
#define HWSZ (HH * WW)        // 16384
#define NC 128
#define SEM_CH (NUM_OP + 2)   // 8

__device__ float g_actv[NB][NHIDDEN];
__device__ float g_gw[NB][NUM_OP];
__device__ float g_bw[NB][NUM_OP];
__device__ float g_wrsum;
__device__ float g_br;

// ---------------------------------------------------------------------------
// Kernel 1a: actv[b][n] = bs[n] + lang[b,:] . Ws[n,:]  for all 4 batches.
// Grid = 8 blocks x 256 threads. Block q handles rows [16q, 16q+16).
// Ws is read exactly ONCE chip-wide; all loads coalesced.
// ---------------------------------------------------------------------------
__global__ __launch_bounds__(256) void coef1_kernel(
    const float* __restrict__ lang,
    const float* __restrict__ Ws, const float* __restrict__ bs) {
    const int q    = blockIdx.x;       // 0..7
    const int tid  = threadIdx.x;
    const int warp = tid >> 5;         // 0..7
    const int lane = tid & 31;

    __shared__ float slang[NB][LANG_DIM];
    // stage all 4 lang vectors (1024 floats, coalesced)
#pragma unroll
    for (int i = 0; i < 4; ++i) {
        int idx = tid + 256 * i;
        slang[idx >> 8][idx & 255] = lang[idx];   // lang is (NB, LANG_DIM) contiguous
    }
    __syncthreads();

    // warp handles rows n0, n0+1 with 2-row x 4-batch ILP (MLP = 16 loads)
    const int n0 = 16 * q + 2 * warp;
    const float* w0 = Ws + (size_t)n0 * LANG_DIM;
    const float* w1 = w0 + LANG_DIM;

    float p[2][NB];
#pragma unroll
    for (int r = 0; r < 2; ++r)
#pragma unroll
        for (int b = 0; b < NB; ++b) p[r][b] = 0.0f;

#pragma unroll
    for (int j = 0; j < LANG_DIM / 32; ++j) {
        const int idx = lane + 32 * j;
        const float wv0 = w0[idx];
        const float wv1 = w1[idx];
#pragma unroll
        for (int b = 0; b < NB; ++b) {
            const float lv = slang[b][idx];
            p[0][b] += wv0 * lv;
            p[1][b] += wv1 * lv;
        }
    }
#pragma unroll
    for (int off = 16; off > 0; off >>= 1)
#pragma unroll
        for (int r = 0; r < 2; ++r)
#pragma unroll
            for (int b = 0; b < NB; ++b)
                p[r][b] += __shfl_xor_sync(0xFFFFFFFFu, p[r][b], off);

    if (lane == 0) {
#pragma unroll
        for (int r = 0; r < 2; ++r) {
            const float bias = bs[n0 + r];
#pragma unroll
            for (int b = 0; b < NB; ++b)
                g_actv[b][n0 + r] = p[r][b] + bias;
        }
    }
}

// ---------------------------------------------------------------------------
// Kernel 1b: fold gamma/beta with Wr. Grid = 4 blocks x 224 threads.
// Warp k (k<6): gw[b][k] = (bg[k] + actv.Wg[k,:]) * Wr[k], same for bw.
// ---------------------------------------------------------------------------
__global__ __launch_bounds__(224) void coef2_kernel(
    const float* __restrict__ Wg, const float* __restrict__ bg,
    const float* __restrict__ Wb, const float* __restrict__ bb,
    const float* __restrict__ Wr, const float* __restrict__ br) {
    const int b    = blockIdx.x;
    const int warp = threadIdx.x >> 5;
    const int lane = threadIdx.x & 31;

    if (warp < NUM_OP) {
        const int k = warp;
        const float* wgr = Wg + k * NHIDDEN;
        const float* wbr = Wb + k * NHIDDEN;
        float pg = 0.0f, pb = 0.0f;
#pragma unroll
        for (int j = 0; j < NHIDDEN / 32; ++j) {
            const float a = g_actv[b][lane + 32 * j];
            pg += a * wgr[lane + 32 * j];
            pb += a * wbr[lane + 32 * j];
        }
#pragma unroll
        for (int off = 16; off > 0; off >>= 1) {
            pg += __shfl_xor_sync(0xFFFFFFFFu, pg, off);
            pb += __shfl_xor_sync(0xFFFFFFFFu, pb, off);
        }
        if (lane == 0) {
            const float wr = Wr[k];
            g_gw[b][k] = (pg + bg[k]) * wr;
            g_bw[b][k] = (pb + bb[k]) * wr;
        }
    } else if (lane == 0 && b == 0) {   // warp 6
        float s = 0.0f;
#pragma unroll
        for (int k = 0; k < NUM_OP; ++k) s += Wr[k];
        g_wrsum = s;
        g_br = br[0];
    }
}

// ---------------------------------------------------------------------------
// Kernel 2: out[b,c,hw] = x[b,c,hw]*scale[b,hw] + shift[b,hw]
// Grid: (16, 4, 16) = 1024 blocks x 256 threads -> ~7 blocks/SM.
// ---------------------------------------------------------------------------
#define CCHUNK 8
#define TPB 256

__global__ __launch_bounds__(TPB) void main_kernel(const float* __restrict__ x,
                                                   const float* __restrict__ sem,
                                                   float* __restrict__ out) {
    const int b   = blockIdx.y;
    const int c0  = blockIdx.z * CCHUNK;
    const int hw4 = blockIdx.x * TPB + threadIdx.x;   // [0, HWSZ/4)

    float gw[NUM_OP], bw[NUM_OP];
#pragma unroll
    for (int k = 0; k < NUM_OP; ++k) { gw[k] = g_gw[b][k]; bw[k] = g_bw[b][k]; }

    float4 scale = make_float4(g_wrsum, g_wrsum, g_wrsum, g_wrsum);
    float4 shift = make_float4(g_br, g_br, g_br, g_br);

    const float4* semb =
        reinterpret_cast<const float4*>(sem + (size_t)b * SEM_CH * HWSZ + 2 * HWSZ) + hw4;
#pragma unroll
    for (int k = 0; k < NUM_OP; ++k) {
        float4 s = semb[(size_t)k * (HWSZ / 4)];
        scale.x += gw[k] * s.x;  scale.y += gw[k] * s.y;
        scale.z += gw[k] * s.z;  scale.w += gw[k] * s.w;
        shift.x += bw[k] * s.x;  shift.y += bw[k] * s.y;
        shift.z += bw[k] * s.z;  shift.w += bw[k] * s.w;
    }

    const float4* xb = reinterpret_cast<const float4*>(x + (size_t)b * NC * HWSZ) + hw4;
    float4*       ob = reinterpret_cast<float4*>(out + (size_t)b * NC * HWSZ) + hw4;

#pragma unroll
    for (int c = c0; c < c0 + CCHUNK; ++c) {
        float4 xv = xb[(size_t)c * (HWSZ / 4)];
        float4 o;
        o.x = xv.x * scale.x + shift.x;
        o.y = xv.y * scale.y + shift.y;
        o.z = xv.z * scale.z + shift.z;
        o.w = xv.w * scale.w + shift.w;
        ob[(size_t)c * (HWSZ / 4)] = o;
    }
}

// ---------------------------------------------------------------------------
extern "C" void kernel_launch(void* const* d_in, const int* in_sizes, int n_in,
                              void* d_out, int out_size) {
    const float* x    = (const float*)d_in[0];
    const float* lang = (const float*)d_in[1];
    const float* sem  = (const float*)d_in[2];
    const float* Ws   = (const float*)d_in[3];
    const float* bs   = (const float*)d_in[4];
    const float* Wg   = (const float*)d_in[5];
    const float* bg   = (const float*)d_in[6];
    const float* Wb   = (const float*)d_in[7];
    const float* bb   = (const float*)d_in[8];
    const float* Wr   = (const float*)d_in[9];
    const float* br   = (const float*)d_in[10];
    float* out = (float*)d_out;

    coef1_kernel<<<8, 256>>>(lang, Ws, bs);
    coef2_kernel<<<NB, 224>>>(Wg, bg, Wb, bb, Wr, br);

    dim3 grid(HWSZ / 4 / TPB, NB, NC / CCHUNK);
    main_kernel<<<grid, TPB>>>(x, sem, out);
}